// round 10
// baseline (speedup 1.0000x reference)
#include <cuda_runtime.h>

#define BH     32
#define LSEQ   4096
#define D      128
#define C      32
#define NCHUNK 128
#define NSPLIT 4

typedef unsigned long long ull;

// Scratch (device globals are the allowed scratch mechanism)
__device__ __align__(16) float g_qt[(size_t)BH * LSEQ * D];   // [bh][chunk][d*32+c] (transposed)
__device__ __align__(16) float g_kn[(size_t)BH * LSEQ * D];   // row-major normalized k
__device__ __align__(16) float g_u [(size_t)BH * LSEQ * D];   // u0 from chunk_kernel; overwritten with u_i by scan
__device__ __align__(16) float g_wt[(size_t)BH * LSEQ * D];   // [bh][chunk][d*32+c] (transposed)
__device__ __align__(16) float g_attn[(size_t)BH * NCHUNK * C * C];  // attn^T: [t][c]
__device__ __align__(16) float g_S[(size_t)BH * NCHUNK * D * D];     // S entering each chunk ([bh][ch][d][dv]); [*][0] unused

// ---------------------------------------------------------------------------
// f32x2 packed helpers
// ---------------------------------------------------------------------------
__device__ __forceinline__ void fma2(ull& acc, ull a, ull b) {
    asm("fma.rn.f32x2 %0, %1, %2, %0;" : "+l"(acc) : "l"(a), "l"(b));
}
__device__ __forceinline__ ull packdup(float s) {
    ull r;
    asm("mov.b64 %0, {%1, %1};" : "=l"(r) : "r"(__float_as_uint(s)));
    return r;
}
__device__ __forceinline__ ull pack2(float lo, float hi) {
    ull r;
    asm("mov.b64 %0, {%1, %2};" : "=l"(r) : "r"(__float_as_uint(lo)), "r"(__float_as_uint(hi)));
    return r;
}
__device__ __forceinline__ void unpack2(ull v, float& lo, float& hi) {
    unsigned a, b;
    asm("mov.b64 {%0, %1}, %2;" : "=r"(a), "=r"(b) : "l"(v));
    lo = __uint_as_float(a); hi = __uint_as_float(b);
}

// ---------------------------------------------------------------------------
// Kernel 1 (fused norm + chunk): unchanged from R9 (passed).
// ---------------------------------------------------------------------------
__global__ void chunk_kernel(const float* __restrict__ q,
                             const float* __restrict__ k,
                             const float* __restrict__ v,
                             const float* __restrict__ beta) {
    __shared__ float knT[128 * 33];
    __shared__ float qnT[128 * 33];
    __shared__ float A[32 * 33];
    __shared__ float beta_s[32];

    int tid = threadIdx.x;
    int lane = tid & 31, wrp = tid >> 5;
    size_t cid = blockIdx.x;
    size_t base = cid * 32;

    const float4* q4 = (const float4*)q;
    const float4* k4 = (const float4*)k;
    float4* gkn4 = (float4*)g_kn;
    #pragma unroll
    for (int rr = 0; rr < 8; rr++) {
        int r = wrp * 8 + rr;
        {
            float4 kk = k4[(base + r) * 32 + lane];
            float ss = kk.x * kk.x + kk.y * kk.y + kk.z * kk.z + kk.w * kk.w;
            #pragma unroll
            for (int o = 16; o; o >>= 1) ss += __shfl_xor_sync(0xffffffffu, ss, o);
            float rn = rsqrtf(ss + 1e-6f);
            kk.x *= rn; kk.y *= rn; kk.z *= rn; kk.w *= rn;
            gkn4[(base + r) * 32 + lane] = kk;
            knT[(lane * 4 + 0) * 33 + r] = kk.x;
            knT[(lane * 4 + 1) * 33 + r] = kk.y;
            knT[(lane * 4 + 2) * 33 + r] = kk.z;
            knT[(lane * 4 + 3) * 33 + r] = kk.w;
        }
        {
            float4 qq = q4[(base + r) * 32 + lane];
            float ss = qq.x * qq.x + qq.y * qq.y + qq.z * qq.z + qq.w * qq.w;
            #pragma unroll
            for (int o = 16; o; o >>= 1) ss += __shfl_xor_sync(0xffffffffu, ss, o);
            float rn = rsqrtf(ss + 1e-6f);
            qq.x *= rn; qq.y *= rn; qq.z *= rn; qq.w *= rn;
            qnT[(lane * 4 + 0) * 33 + r] = qq.x;
            qnT[(lane * 4 + 1) * 33 + r] = qq.y;
            qnT[(lane * 4 + 2) * 33 + r] = qq.z;
            qnT[(lane * 4 + 3) * 33 + r] = qq.w;
        }
    }
    if (tid < 32) beta_s[tid] = beta[base + tid];
    __syncthreads();

    int j = lane, iw = wrp;

    {
        float acc[8] = {0, 0, 0, 0, 0, 0, 0, 0};
        for (int d = 0; d < 128; d++) {
            float kj = knT[d * 33 + j];
            #pragma unroll
            for (int ii = 0; ii < 8; ii++)
                acc[ii] += knT[d * 33 + (iw * 8 + ii)] * kj;
        }
        #pragma unroll
        for (int ii = 0; ii < 8; ii++) {
            int i = iw * 8 + ii;
            A[i * 33 + j] = (i > j) ? (-beta_s[i] * acc[ii]) : 0.0f;
        }
    }
    __syncthreads();

    if (tid < 32) {
        for (int i = 1; i < 32; i++) {
            float upd = 0.0f;
            for (int t = tid + 1; t < i; t++)
                upd += A[i * 33 + t] * A[t * 33 + tid];
            __syncwarp();
            if (tid < i) A[i * 33 + tid] += upd;
            __syncwarp();
        }
    }
    __syncthreads();

    {
        float acc[8] = {0, 0, 0, 0, 0, 0, 0, 0};
        for (int d = 0; d < 128; d++) {
            float qv = qnT[d * 33 + lane];
            #pragma unroll
            for (int ii = 0; ii < 8; ii++)
                acc[ii] += knT[d * 33 + (iw * 8 + ii)] * qv;
        }
        float* ga = g_attn + cid * 1024;
        #pragma unroll
        for (int ii = 0; ii < 8; ii++) {
            int jr = iw * 8 + ii;
            ga[jr * 32 + lane] = (lane >= jr) ? acc[ii] : 0.0f;
        }
        float* gq = g_qt + base * 128;
        for (int idx = tid; idx < 4096; idx += 128) {
            int d = idx >> 5, c = idx & 31;
            gq[idx] = qnT[d * 33 + c];
        }
    }
    __syncthreads();

    {
        int d32 = lane;
        int cw  = wrp;
        float4 au[8], aw[8];
        #pragma unroll
        for (int ii = 0; ii < 8; ii++) {
            int c = cw * 8 + ii;
            float4 vv = *(const float4*)&v[(base + c) * 128 + d32 * 4];
            float4 kk = *(const float4*)&g_kn[(base + c) * 128 + d32 * 4];
            float bc = beta_s[c];
            au[ii] = make_float4(vv.x * bc, vv.y * bc, vv.z * bc, vv.w * bc);
            aw[ii] = make_float4(kk.x * bc, kk.y * bc, kk.z * bc, kk.w * bc);
        }
        for (int t = 0; t < 32; t++) {
            float bt = beta_s[t];
            float4 vv = *(const float4*)&v[(base + t) * 128 + d32 * 4];
            float4 kk = *(const float4*)&g_kn[(base + t) * 128 + d32 * 4];
            vv.x *= bt; vv.y *= bt; vv.z *= bt; vv.w *= bt;
            kk.x *= bt; kk.y *= bt; kk.z *= bt; kk.w *= bt;
            #pragma unroll
            for (int ii = 0; ii < 8; ii++) {
                float a = A[(cw * 8 + ii) * 33 + t];
                au[ii].x += a * vv.x; au[ii].y += a * vv.y;
                au[ii].z += a * vv.z; au[ii].w += a * vv.w;
                aw[ii].x += a * kk.x; aw[ii].y += a * kk.y;
                aw[ii].z += a * kk.z; aw[ii].w += a * kk.w;
            }
        }
        #pragma unroll
        for (int ii = 0; ii < 8; ii++) {
            int c = cw * 8 + ii;
            *(float4*)&g_u[(base + c) * 128 + d32 * 4] = au[ii];
            knT[(d32 * 4 + 0) * 33 + c] = aw[ii].x;
            knT[(d32 * 4 + 1) * 33 + c] = aw[ii].y;
            knT[(d32 * 4 + 2) * 33 + c] = aw[ii].z;
            knT[(d32 * 4 + 3) * 33 + c] = aw[ii].w;
        }
    }
    __syncthreads();
    {
        float* gw = g_wt + base * 128;
        for (int idx = tid; idx < 4096; idx += 128) {
            int d = idx >> 5, c = idx & 31;
            gw[idx] = knT[d * 33 + c];
        }
    }
}

// ---------------------------------------------------------------------------
// cp.async helpers
// ---------------------------------------------------------------------------
__device__ __forceinline__ void cpa16(float* s, const void* g) {
    unsigned a = (unsigned)__cvta_generic_to_shared(s);
    asm volatile("cp.async.cg.shared.global [%0], [%1], 16;" :: "r"(a), "l"(g));
}
__device__ __forceinline__ void cpa_commit() {
    asm volatile("cp.async.commit_group;");
}
__device__ __forceinline__ void cpa_wait_all() {
    asm volatile("cp.async.wait_group 0;");
}

// Scan buffer layout (floats, per buffer): k[4096] @0, wT[4096] @4096, u0[1024] @8192
#define OFF_K    0
#define OFF_W    4096
#define OFF_U0   8192
#define BUF_FLOATS 9216

// ---------------------------------------------------------------------------
// Kernel 2: minimal sequential scan. grid (NSPLIT, BH), 256 threads.
// Per chunk: u_i = u0 - w@S (store to g_u); S += k^T@u (store S_in of next
// chunk to g_S). Output projection is NOT here (out_kernel below).
// ---------------------------------------------------------------------------
__global__ void __launch_bounds__(256, 1) scan_kernel() {
    extern __shared__ float sm[];
    float* S  = sm;                             // [d=128][j=32]
    float* us = sm + 4096 + 2 * BUF_FLOATS;     // [c=32][j=32]

    int tid = threadIdx.x;
    int bh = blockIdx.y;
    int dvoff = blockIdx.x * 32;
    int j = tid & 31;              // dv column within slice
    int cg = tid >> 5;             // warp id 0..7: rows c = cg*4 .. cg*4+3

    const float4* gk4 = (const float4*)(g_kn + (size_t)bh * LSEQ * D);
    const float4* gw4 = (const float4*)(g_wt + (size_t)bh * LSEQ * D);
    float* gu = g_u + (size_t)bh * LSEQ * D;          // read u0, write u
    float* gS = g_S + (size_t)bh * NCHUNK * D * D;    // write S_in per chunk

    // ---- prefetch chunk 0 into buffer 0
    {
        float* B = sm + 4096;
        for (int i = tid; i < 1024; i += 256) {
            cpa16(B + OFF_K + 4 * i, gk4 + i);
            cpa16(B + OFF_W + 4 * i, gw4 + i);
        }
        int row = tid >> 3, c4 = tid & 7;
        cpa16(B + OFF_U0 + 4 * tid,
              gu + (size_t)row * 128 + dvoff + c4 * 4);
        cpa_commit();
    }

    for (int i = tid; i < 4096; i += 256) S[i] = 0.0f;

    for (int ch = 0; ch < NCHUNK; ch++) {
        cpa_wait_all();
        __syncthreads();   // current buffer ready; prev chunk's S update done

        float* B = sm + 4096 + (ch & 1) * BUF_FLOATS;
        const ulonglong2* kk2 = (const ulonglong2*)(B + OFF_K);
        const ulonglong2* wT2 = (const ulonglong2*)(B + OFF_W);
        const float*      u0b = B + OFF_U0;

        // ---- prefetch chunk ch+1 into the other buffer (overlaps compute)
        if (ch + 1 < NCHUNK) {
            float* P = sm + 4096 + ((ch + 1) & 1) * BUF_FLOATS;
            size_t off4 = (size_t)(ch + 1) * 1024;
            for (int i = tid; i < 1024; i += 256) {
                cpa16(P + OFF_K + 4 * i, gk4 + off4 + i);
                cpa16(P + OFF_W + 4 * i, gw4 + off4 + i);
            }
            int row = tid >> 3, c4 = tid & 7;
            cpa16(P + OFF_U0 + 4 * tid,
                  gu + (size_t)((ch + 1) * 32 + row) * 128 + dvoff + c4 * 4);
            cpa_commit();
        }

        // ---- MW = w@S (packed pairs over c)
        ull MW01 = 0, MW23 = 0;
        #pragma unroll 8
        for (int d = 0; d < 128; d++) {
            ull sd = packdup(S[d * 32 + j]);
            ulonglong2 wv = wT2[d * 8 + cg];   // (w[c0],w[c1]),(w[c2],w[c3]) at this d
            fma2(MW01, wv.x, sd);
            fma2(MW23, wv.y, sd);
        }
        {   // u_c = u0_c - MW_c  -> us (smem) and g_u (for out_kernel)
            float m0, m1, m2, m3;
            unpack2(MW01, m0, m1);
            unpack2(MW23, m2, m3);
            float u0 = u0b[(cg * 4 + 0) * 32 + j] - m0;
            float u1 = u0b[(cg * 4 + 1) * 32 + j] - m1;
            float u2 = u0b[(cg * 4 + 2) * 32 + j] - m2;
            float u3 = u0b[(cg * 4 + 3) * 32 + j] - m3;
            us[(cg * 4 + 0) * 32 + j] = u0;
            us[(cg * 4 + 1) * 32 + j] = u1;
            us[(cg * 4 + 2) * 32 + j] = u2;
            us[(cg * 4 + 3) * 32 + j] = u3;
            gu[(size_t)(ch * 32 + cg * 4 + 0) * 128 + dvoff + j] = u0;
            gu[(size_t)(ch * 32 + cg * 4 + 1) * 128 + dvoff + j] = u1;
            gu[(size_t)(ch * 32 + cg * 4 + 2) * 128 + dvoff + j] = u2;
            gu[(size_t)(ch * 32 + cg * 4 + 3) * 128 + dvoff + j] = u3;
        }
        __syncthreads();   // us ready; all S reads of this chunk complete

        // ---- S += k^T @ u  (16 disjoint S rows per warp, packed over d pairs)
        int dbase = cg * 16;
        ull SP[8];
        #pragma unroll
        for (int p = 0; p < 8; p++)
            SP[p] = pack2(S[(dbase + 2 * p) * 32 + j],
                          S[(dbase + 2 * p + 1) * 32 + j]);
        #pragma unroll 2
        for (int c = 0; c < 32; c++) {
            ull ud = packdup(us[c * 32 + j]);
            #pragma unroll
            for (int qq = 0; qq < 4; qq++) {
                ulonglong2 kv = kk2[c * 32 + cg * 4 + qq];
                fma2(SP[2 * qq + 0], kv.x, ud);
                fma2(SP[2 * qq + 1], kv.y, ud);
            }
        }
        float* gSn = gS + (size_t)(ch + 1) * D * D;   // S entering chunk ch+1
        #pragma unroll
        for (int p = 0; p < 8; p++) {
            float a, b;
            unpack2(SP[p], a, b);
            S[(dbase + 2 * p) * 32 + j]     = a;
            S[(dbase + 2 * p + 1) * 32 + j] = b;
            if (ch + 1 < NCHUNK) {
                gSn[(size_t)(dbase + 2 * p) * 128 + dvoff + j]     = a;
                gSn[(size_t)(dbase + 2 * p + 1) * 128 + dvoff + j] = b;
            }
        }
        // next iteration's top barrier orders these writes before S reads
    }
}

// ---------------------------------------------------------------------------
// Kernel 3: fully parallel output projection.
//   out[ch] = q_ch @ S_in[ch] + attn_ch @ u_ch
// grid (NSPLIT, NCHUNK, BH), 256 threads. 40KB static smem -> multi-block/SM.
// ---------------------------------------------------------------------------
__global__ void __launch_bounds__(256) out_kernel(float* __restrict__ out) {
    __shared__ float Ssm[4096];    // [d=128][e=32] slice
    __shared__ float qTsm[4096];   // [d*32+c]
    __shared__ float aTsm[1024];   // attn^T [t*32+c]
    __shared__ float usm[1024];    // [t=32][e=32] slice

    int tid = threadIdx.x;
    int j = tid & 31;              // e column within slice
    int cg = tid >> 5;             // warp id: rows c = cg*4..cg*4+3
    int eoff = blockIdx.x * 32;
    int ch   = blockIdx.y;
    int bh   = blockIdx.z;

    const float* gS = g_S + ((size_t)bh * NCHUNK + ch) * D * D;
    const float4* gq4 = (const float4*)(g_qt + ((size_t)bh * NCHUNK + ch) * C * D);
    const float4* ga4 = (const float4*)(g_attn + ((size_t)bh * NCHUNK + ch) * C * C);
    const float* gu = g_u + (size_t)bh * LSEQ * D;

    // ---- stage inputs
    if (ch > 0) {
        for (int i = tid; i < 1024; i += 256) {
            int d = i >> 3, c4 = i & 7;
            cpa16(&Ssm[d * 32 + c4 * 4], gS + (size_t)d * 128 + eoff + c4 * 4);
        }
    }
    for (int i = tid; i < 1024; i += 256)
        cpa16(&qTsm[4 * i], gq4 + i);
    cpa16(&aTsm[4 * tid], ga4 + tid);
    {
        int t = tid >> 3, c4 = tid & 7;
        cpa16(&usm[t * 32 + c4 * 4],
              gu + (size_t)(ch * 32 + t) * 128 + eoff + c4 * 4);
    }
    cpa_commit();
    cpa_wait_all();
    __syncthreads();

    ull O01 = 0, O23 = 0;
    if (ch > 0) {
        #pragma unroll 8
        for (int d = 0; d < 128; d++) {
            ull sd = packdup(Ssm[d * 32 + j]);
            ulonglong2 qv = ((const ulonglong2*)qTsm)[d * 8 + cg];
            fma2(O01, qv.x, sd);
            fma2(O23, qv.y, sd);
        }
    }
    #pragma unroll 4
    for (int t = 0; t < 32; t++) {
        ull ud = packdup(usm[t * 32 + j]);
        ulonglong2 av = ((const ulonglong2*)aTsm)[t * 8 + cg];
        fma2(O01, av.x, ud);
        fma2(O23, av.y, ud);
    }
    float o0, o1, o2, o3;
    unpack2(O01, o0, o1);
    unpack2(O23, o2, o3);
    float* go = out + (size_t)bh * LSEQ * D + eoff;
    go[(size_t)(ch * 32 + cg * 4 + 0) * 128 + j] = o0;
    go[(size_t)(ch * 32 + cg * 4 + 1) * 128 + j] = o1;
    go[(size_t)(ch * 32 + cg * 4 + 2) * 128 + j] = o2;
    go[(size_t)(ch * 32 + cg * 4 + 3) * 128 + j] = o3;
}

// ---------------------------------------------------------------------------
extern "C" void kernel_launch(void* const* d_in, const int* in_sizes, int n_in,
                              void* d_out, int out_size) {
    const float* q    = (const float*)d_in[0];
    const float* k    = (const float*)d_in[1];
    const float* v    = (const float*)d_in[2];
    const float* beta = (const float*)d_in[3];
    float* out = (float*)d_out;

    chunk_kernel<<<BH * NCHUNK, 128>>>(q, k, v, beta);

    const int smem_bytes = (4096 + 2 * BUF_FLOATS + 1024) * sizeof(float); // 94 KB
    cudaFuncSetAttribute(scan_kernel,
                         cudaFuncAttributeMaxDynamicSharedMemorySize, smem_bytes);
    scan_kernel<<<dim3(NSPLIT, BH), 256, smem_bytes>>>();

    out_kernel<<<dim3(NSPLIT, NCHUNK, BH), 256>>>(out);
}

// round 11
// speedup vs baseline: 1.0923x; 1.0923x over previous
#include <cuda_runtime.h>

#define BH     32
#define LSEQ   4096
#define D      128
#define C      32
#define NCHUNK 128
#define NSPLIT 4

typedef unsigned long long ull;

// Scratch (device globals are the allowed scratch mechanism)
__device__ __align__(16) float g_qt[(size_t)BH * LSEQ * D];   // [bh][chunk][d*32+c] (transposed)
__device__ __align__(16) float g_kn[(size_t)BH * LSEQ * D];   // row-major normalized k
__device__ __align__(16) float g_u [(size_t)BH * LSEQ * D];   // u0 from chunk_kernel
__device__ __align__(16) float g_wt[(size_t)BH * LSEQ * D];   // [bh][chunk][d*32+c] (transposed)
__device__ __align__(16) float g_attn[(size_t)BH * NCHUNK * C * C];  // attn^T: [t][c]

// ---------------------------------------------------------------------------
// f32x2 packed helpers
// ---------------------------------------------------------------------------
__device__ __forceinline__ void fma2(ull& acc, ull a, ull b) {
    asm("fma.rn.f32x2 %0, %1, %2, %0;" : "+l"(acc) : "l"(a), "l"(b));
}
__device__ __forceinline__ ull packdup(float s) {
    ull r;
    asm("mov.b64 %0, {%1, %1};" : "=l"(r) : "r"(__float_as_uint(s)));
    return r;
}
__device__ __forceinline__ ull pack2(float lo, float hi) {
    ull r;
    asm("mov.b64 %0, {%1, %2};" : "=l"(r) : "r"(__float_as_uint(lo)), "r"(__float_as_uint(hi)));
    return r;
}
__device__ __forceinline__ void unpack2(ull v, float& lo, float& hi) {
    unsigned a, b;
    asm("mov.b64 {%0, %1}, %2;" : "=r"(a), "=r"(b) : "l"(v));
    lo = __uint_as_float(a); hi = __uint_as_float(b);
}

// ---------------------------------------------------------------------------
// Kernel 1 (fused norm + chunk). 4096 blocks, 128 threads.
// Forward substitution (warp 0) now overlaps with attn^T + q^T drain (warps 1-3).
// ---------------------------------------------------------------------------
__global__ void chunk_kernel(const float* __restrict__ q,
                             const float* __restrict__ k,
                             const float* __restrict__ v,
                             const float* __restrict__ beta) {
    __shared__ float knT[128 * 33];
    __shared__ float qnT[128 * 33];
    __shared__ float A[32 * 33];
    __shared__ float beta_s[32];

    int tid = threadIdx.x;
    int lane = tid & 31, wrp = tid >> 5;
    size_t cid = blockIdx.x;
    size_t base = cid * 32;

    // ---- Phase 1: load + l2-normalize (warp per row, 8 rows/warp)
    const float4* q4 = (const float4*)q;
    const float4* k4 = (const float4*)k;
    float4* gkn4 = (float4*)g_kn;
    #pragma unroll
    for (int rr = 0; rr < 8; rr++) {
        int r = wrp * 8 + rr;
        {
            float4 kk = k4[(base + r) * 32 + lane];
            float ss = kk.x * kk.x + kk.y * kk.y + kk.z * kk.z + kk.w * kk.w;
            #pragma unroll
            for (int o = 16; o; o >>= 1) ss += __shfl_xor_sync(0xffffffffu, ss, o);
            float rn = rsqrtf(ss + 1e-6f);
            kk.x *= rn; kk.y *= rn; kk.z *= rn; kk.w *= rn;
            gkn4[(base + r) * 32 + lane] = kk;
            knT[(lane * 4 + 0) * 33 + r] = kk.x;
            knT[(lane * 4 + 1) * 33 + r] = kk.y;
            knT[(lane * 4 + 2) * 33 + r] = kk.z;
            knT[(lane * 4 + 3) * 33 + r] = kk.w;
        }
        {
            float4 qq = q4[(base + r) * 32 + lane];
            float ss = qq.x * qq.x + qq.y * qq.y + qq.z * qq.z + qq.w * qq.w;
            #pragma unroll
            for (int o = 16; o; o >>= 1) ss += __shfl_xor_sync(0xffffffffu, ss, o);
            float rn = rsqrtf(ss + 1e-6f);
            qq.x *= rn; qq.y *= rn; qq.z *= rn; qq.w *= rn;
            qnT[(lane * 4 + 0) * 33 + r] = qq.x;
            qnT[(lane * 4 + 1) * 33 + r] = qq.y;
            qnT[(lane * 4 + 2) * 33 + r] = qq.z;
            qnT[(lane * 4 + 3) * 33 + r] = qq.w;
        }
    }
    if (tid < 32) beta_s[tid] = beta[base + tid];
    __syncthreads();

    int j = lane, iw = wrp;

    // ---- Phase 2: A = -(beta_i * kn_i . kn_j), strictly lower (all warps)
    {
        float acc[8] = {0, 0, 0, 0, 0, 0, 0, 0};
        for (int d = 0; d < 128; d++) {
            float kj = knT[d * 33 + j];
            #pragma unroll
            for (int ii = 0; ii < 8; ii++)
                acc[ii] += knT[d * 33 + (iw * 8 + ii)] * kj;
        }
        #pragma unroll
        for (int ii = 0; ii < 8; ii++) {
            int i = iw * 8 + ii;
            A[i * 33 + j] = (i > j) ? (-beta_s[i] * acc[ii]) : 0.0f;
        }
    }
    __syncthreads();

    // ---- Phase 3 (overlapped): warp 0 -> forward substitution on A;
    //      warps 1-3 -> attn^T (independent of A) + q^T drain.
    if (wrp == 0) {
        for (int i = 1; i < 32; i++) {
            float upd = 0.0f;
            for (int t = lane + 1; t < i; t++)
                upd += A[i * 33 + t] * A[t * 33 + lane];
            __syncwarp();
            if (lane < i) A[i * 33 + lane] += upd;
            __syncwarp();
        }
    } else {
        // attn rows split 11/11/10 across warps 1..3
        int r0 = (wrp - 1) * 11;
        int nr = (wrp == 3) ? 10 : 11;
        float acc[11];
        #pragma unroll
        for (int ii = 0; ii < 11; ii++) acc[ii] = 0.0f;
        for (int d = 0; d < 128; d++) {
            float qv = qnT[d * 33 + lane];
            #pragma unroll
            for (int ii = 0; ii < 11; ii++)
                if (ii < nr)
                    acc[ii] += knT[d * 33 + (r0 + ii)] * qv;
        }
        float* ga = g_attn + cid * 1024;
        #pragma unroll
        for (int ii = 0; ii < 11; ii++) {
            if (ii < nr) {
                int jr = r0 + ii;
                ga[jr * 32 + lane] = (lane >= jr) ? acc[ii] : 0.0f;
            }
        }
        // q^T drain (warps 1-3, 96 threads)
        float* gq = g_qt + base * 128;
        for (int idx = tid - 32; idx < 4096; idx += 96) {
            int d = idx >> 5, c = idx & 31;
            gq[idx] = qnT[d * 33 + c];
        }
    }
    __syncthreads();

    // ---- Phase 4: u = (A+I)@(beta*v) -> g_u; w = (A+I)@(beta*kn) -> g_wt (transposed)
    {
        int d32 = lane;
        int cw  = wrp;
        float4 au[8], aw[8];
        #pragma unroll
        for (int ii = 0; ii < 8; ii++) {
            int c = cw * 8 + ii;
            float4 vv = *(const float4*)&v[(base + c) * 128 + d32 * 4];
            float4 kk = *(const float4*)&g_kn[(base + c) * 128 + d32 * 4];
            float bc = beta_s[c];
            au[ii] = make_float4(vv.x * bc, vv.y * bc, vv.z * bc, vv.w * bc);
            aw[ii] = make_float4(kk.x * bc, kk.y * bc, kk.z * bc, kk.w * bc);
        }
        for (int t = 0; t < 32; t++) {
            float bt = beta_s[t];
            float4 vv = *(const float4*)&v[(base + t) * 128 + d32 * 4];
            float4 kk = *(const float4*)&g_kn[(base + t) * 128 + d32 * 4];
            vv.x *= bt; vv.y *= bt; vv.z *= bt; vv.w *= bt;
            kk.x *= bt; kk.y *= bt; kk.z *= bt; kk.w *= bt;
            #pragma unroll
            for (int ii = 0; ii < 8; ii++) {
                float a = A[(cw * 8 + ii) * 33 + t];
                au[ii].x += a * vv.x; au[ii].y += a * vv.y;
                au[ii].z += a * vv.z; au[ii].w += a * vv.w;
                aw[ii].x += a * kk.x; aw[ii].y += a * kk.y;
                aw[ii].z += a * kk.z; aw[ii].w += a * kk.w;
            }
        }
        #pragma unroll
        for (int ii = 0; ii < 8; ii++) {
            int c = cw * 8 + ii;
            *(float4*)&g_u[(base + c) * 128 + d32 * 4] = au[ii];
            knT[(d32 * 4 + 0) * 33 + c] = aw[ii].x;
            knT[(d32 * 4 + 1) * 33 + c] = aw[ii].y;
            knT[(d32 * 4 + 2) * 33 + c] = aw[ii].z;
            knT[(d32 * 4 + 3) * 33 + c] = aw[ii].w;
        }
    }
    __syncthreads();
    {
        float* gw = g_wt + base * 128;
        for (int idx = tid; idx < 4096; idx += 128) {
            int d = idx >> 5, c = idx & 31;
            gw[idx] = knT[d * 33 + c];
        }
    }
}

// ---------------------------------------------------------------------------
// cp.async helpers
// ---------------------------------------------------------------------------
__device__ __forceinline__ void cpa16(float* s, const void* g) {
    unsigned a = (unsigned)__cvta_generic_to_shared(s);
    asm volatile("cp.async.cg.shared.global [%0], [%1], 16;" :: "r"(a), "l"(g));
}
__device__ __forceinline__ void cpa_commit() {
    asm volatile("cp.async.commit_group;");
}
__device__ __forceinline__ void cpa_wait_all() {
    asm volatile("cp.async.wait_group 0;");
}

// Scan buffer layout (floats, per buffer):
//   qT[4096] @0, k[4096] @4096, wT[4096] @8192, attnT[1024] @12288
#define OFF_Q    0
#define OFF_K    4096
#define OFF_W    8192
#define OFF_A    12288
#define BUF_FLOATS 13312

// ---------------------------------------------------------------------------
// Kernel 2: sequential scan (R9 structure). grid (NSPLIT, BH), 256 threads.
// u0 read via direct LDG (issued early); attn@u merged into the S-update c-loop.
// ---------------------------------------------------------------------------
__global__ void __launch_bounds__(256, 1) scan_kernel(float* __restrict__ out) {
    extern __shared__ float sm[];
    float* S  = sm;                             // [d=128][j=32]
    float* us = sm + 4096 + 2 * BUF_FLOATS;     // [c=32][j=32]

    int tid = threadIdx.x;
    int bh = blockIdx.y;
    int dvoff = blockIdx.x * 32;
    int j = tid & 31;              // dv column within slice
    int cg = tid >> 5;             // warp id 0..7: rows c = cg*4 .. cg*4+3

    const float4* gq4 = (const float4*)(g_qt + (size_t)bh * LSEQ * D);
    const float4* gk4 = (const float4*)(g_kn + (size_t)bh * LSEQ * D);
    const float4* gw4 = (const float4*)(g_wt + (size_t)bh * LSEQ * D);
    const float4* ga4 = (const float4*)(g_attn + (size_t)bh * NCHUNK * 1024);
    const float*  gu  = g_u + (size_t)bh * LSEQ * D;
    float* gout = out + (size_t)bh * LSEQ * D + dvoff;

    // ---- prefetch chunk 0 into buffer 0
    {
        float* B = sm + 4096;
        for (int i = tid; i < 1024; i += 256) {
            cpa16(B + OFF_Q + 4 * i, gq4 + i);
            cpa16(B + OFF_K + 4 * i, gk4 + i);
            cpa16(B + OFF_W + 4 * i, gw4 + i);
        }
        cpa16(B + OFF_A + 4 * tid, ga4 + tid);
        cpa_commit();
    }

    for (int i = tid; i < 4096; i += 256) S[i] = 0.0f;

    for (int ch = 0; ch < NCHUNK; ch++) {
        cpa_wait_all();
        __syncthreads();   // current buffer ready; prev chunk's S update done

        float* B = sm + 4096 + (ch & 1) * BUF_FLOATS;
        const ulonglong2* qT2 = (const ulonglong2*)(B + OFF_Q);
        const ulonglong2* kk2 = (const ulonglong2*)(B + OFF_K);
        const ulonglong2* wT2 = (const ulonglong2*)(B + OFF_W);
        const ulonglong2* aT2 = (const ulonglong2*)(B + OFF_A);

        // ---- u0 direct LDG, issued early (consumed after fused loop)
        float u00 = gu[(size_t)(ch * 32 + cg * 4 + 0) * 128 + dvoff + j];
        float u01 = gu[(size_t)(ch * 32 + cg * 4 + 1) * 128 + dvoff + j];
        float u02 = gu[(size_t)(ch * 32 + cg * 4 + 2) * 128 + dvoff + j];
        float u03 = gu[(size_t)(ch * 32 + cg * 4 + 3) * 128 + dvoff + j];

        // ---- prefetch chunk ch+1 into the other buffer (overlaps compute)
        if (ch + 1 < NCHUNK) {
            float* P = sm + 4096 + ((ch + 1) & 1) * BUF_FLOATS;
            size_t off4 = (size_t)(ch + 1) * 1024;
            for (int i = tid; i < 1024; i += 256) {
                cpa16(P + OFF_Q + 4 * i, gq4 + off4 + i);
                cpa16(P + OFF_K + 4 * i, gk4 + off4 + i);
                cpa16(P + OFF_W + 4 * i, gw4 + off4 + i);
            }
            cpa16(P + OFF_A + 4 * tid, ga4 + (size_t)(ch + 1) * 256 + tid);
            cpa_commit();
        }

        // ---- fused: MW = w@S, O = q@S (packed pairs over c)
        ull MW01 = 0, MW23 = 0, O01 = 0, O23 = 0;
        #pragma unroll 4
        for (int d = 0; d < 128; d++) {
            ull sd = packdup(S[d * 32 + j]);
            ulonglong2 wv = wT2[d * 8 + cg];
            ulonglong2 qv = qT2[d * 8 + cg];
            fma2(MW01, wv.x, sd);
            fma2(MW23, wv.y, sd);
            fma2(O01, qv.x, sd);
            fma2(O23, qv.y, sd);
        }
        {   // u_c = u0_c - MW_c  -> us
            float m0, m1, m2, m3;
            unpack2(MW01, m0, m1);
            unpack2(MW23, m2, m3);
            us[(cg * 4 + 0) * 32 + j] = u00 - m0;
            us[(cg * 4 + 1) * 32 + j] = u01 - m1;
            us[(cg * 4 + 2) * 32 + j] = u02 - m2;
            us[(cg * 4 + 3) * 32 + j] = u03 - m3;
        }
        __syncthreads();   // us ready; all S reads of this chunk complete

        // ---- merged c-loop: O += attn^T u  AND  S += k^T u (shared us loads)
        int dbase = cg * 16;
        ull SP[8];
        #pragma unroll
        for (int p = 0; p < 8; p++)
            SP[p] = pack2(S[(dbase + 2 * p) * 32 + j],
                          S[(dbase + 2 * p + 1) * 32 + j]);
        #pragma unroll 2
        for (int c = 0; c < 32; c++) {
            ull ud = packdup(us[c * 32 + j]);
            ulonglong2 av = aT2[c * 8 + cg];
            fma2(O01, av.x, ud);
            fma2(O23, av.y, ud);
            #pragma unroll
            for (int qq = 0; qq < 4; qq++) {
                ulonglong2 kv = kk2[c * 32 + cg * 4 + qq];
                fma2(SP[2 * qq + 0], kv.x, ud);
                fma2(SP[2 * qq + 1], kv.y, ud);
            }
        }
        {
            float o0, o1, o2, o3;
            unpack2(O01, o0, o1);
            unpack2(O23, o2, o3);
            gout[(size_t)(ch * 32 + cg * 4 + 0) * 128 + j] = o0;
            gout[(size_t)(ch * 32 + cg * 4 + 1) * 128 + j] = o1;
            gout[(size_t)(ch * 32 + cg * 4 + 2) * 128 + j] = o2;
            gout[(size_t)(ch * 32 + cg * 4 + 3) * 128 + j] = o3;
        }
        #pragma unroll
        for (int p = 0; p < 8; p++) {
            float a, b;
            unpack2(SP[p], a, b);
            S[(dbase + 2 * p) * 32 + j]     = a;
            S[(dbase + 2 * p + 1) * 32 + j] = b;
        }
        // next iteration's top barrier orders these writes before S reads
    }
}

// ---------------------------------------------------------------------------
extern "C" void kernel_launch(void* const* d_in, const int* in_sizes, int n_in,
                              void* d_out, int out_size) {
    const float* q    = (const float*)d_in[0];
    const float* k    = (const float*)d_in[1];
    const float* v    = (const float*)d_in[2];
    const float* beta = (const float*)d_in[3];
    float* out = (float*)d_out;

    chunk_kernel<<<BH * NCHUNK, 128>>>(q, k, v, beta);

    const int smem_bytes = (4096 + 2 * BUF_FLOATS + 1024) * sizeof(float); // ~124 KB
    cudaFuncSetAttribute(scan_kernel,
                         cudaFuncAttributeMaxDynamicSharedMemorySize, smem_bytes);
    scan_kernel<<<dim3(NSPLIT, BH), 256, smem_bytes>>>(out);
}